// round 3
// baseline (speedup 1.0000x reference)
#include <cuda_runtime.h>
#include <cstdint>

#define T_STEPS 100
#define BATCH   4096
#define NIN     784
#define H1      100
#define H2      10
#define BEGIN   20

// ---------------- device scratch (no allocations allowed) ----------------
__device__ uint2 g_keys[T_STEPS];
// exc1 buffer, later reused in-place as delayed-outer (o1d) buffer: [T][B][H1]
__device__ float g_buf1[(size_t)T_STEPS * BATCH * H1];   // 163.84 MB
__device__ float g_exc2[(size_t)T_STEPS * BATCH * H2];   // 16.4 MB

// ---------------- threefry2x32 (JAX-exact, 20 rounds) ----------------
__device__ __forceinline__ void threefry2x32(uint32_t k0, uint32_t k1,
                                             uint32_t x0, uint32_t x1,
                                             uint32_t& o0, uint32_t& o1) {
    uint32_t k2 = k0 ^ k1 ^ 0x1BD11BDAu;
#define TFR(d) { x0 += x1; x1 = __funnelshift_l(x1, x1, (d)); x1 ^= x0; }
    x0 += k0; x1 += k1;
    TFR(13) TFR(15) TFR(26) TFR(6)
    x0 += k1; x1 += k2 + 1u;
    TFR(17) TFR(29) TFR(16) TFR(24)
    x0 += k2; x1 += k0 + 2u;
    TFR(13) TFR(15) TFR(26) TFR(6)
    x0 += k0; x1 += k1 + 3u;
    TFR(17) TFR(29) TFR(16) TFR(24)
    x0 += k1; x1 += k2 + 4u;
    TFR(13) TFR(15) TFR(26) TFR(6)
    x0 += k2; x1 += k0 + 5u;
#undef TFR
    o0 = x0; o1 = x1;
}

// key_t = threefry((0,42), (0,t))  — fold-like split (jax_threefry_partitionable)
__global__ void init_keys_kernel() {
    int t = threadIdx.x;
    if (t < T_STEPS) {
        uint32_t w0, w1;
        threefry2x32(0u, 42u, 0u, (uint32_t)t, w0, w1);
        g_keys[t] = make_uint2(w0, w1);
    }
}

// u32 bits -> uniform [0,1) exactly as jax.random.uniform (f32)
__device__ __forceinline__ float bits_to_uniform(uint32_t bits) {
    return __uint_as_float((bits >> 9) | 0x3f800000u) - 1.0f;
}

// ---------------- fused RNG + GEMM1:  exc1[t,b,h] = (u ⊙ x) @ W1 + b1 ----------------
#define BM  64
#define BK  28
#define BM4 68          // padded A rows (16B-aligned row stride, fewer STS conflicts)
#define GT  320

__global__ __launch_bounds__(GT)
void gemm1_kernel(const float* __restrict__ x, const float* __restrict__ W1,
                  const float* __restrict__ b1) {
    __shared__ float a_s[BK][BM4];   // transposed: a_s[kk][row]
    __shared__ float w_s[BK][H1];

    const int t   = blockIdx.y;
    const int rb  = blockIdx.x;
    const int tid = threadIdx.x;
    const int b0  = rb * BM;

    const uint2 key = g_keys[t];

    const int cg = tid % 20;   // 20 col-groups * 5 cols
    const int rg = tid / 20;   // 16 row-groups * 4 rows

    float acc[4][5];
#pragma unroll
    for (int r = 0; r < 4; r++)
#pragma unroll
        for (int c = 0; c < 5; c++) acc[r][c] = 0.0f;

    for (int k0 = 0; k0 < NIN; k0 += BK) {
        // W tile: [BK][H1], coalesced
        for (int idx = tid; idx < BK * H1; idx += GT) {
            int kk = idx / H1, col = idx % H1;
            w_s[kk][col] = W1[(k0 + kk) * H1 + col];
        }
        // A tile with fused threefry RNG: element (b, j) uses counter i = b*784+j
        for (int q = tid; q < BM * BK; q += GT) {
            int jj = q % BK;           // lane-fast -> coalesced x reads
            int tr = q / BK;
            int b  = b0 + tr;
            int j  = k0 + jj;
            uint32_t i = (uint32_t)(b * NIN + j);
            uint32_t w0, w1;
            threefry2x32(key.x, key.y, 0u, i, w0, w1);
            float u = bits_to_uniform(w0 ^ w1);
            a_s[jj][tr] = u * x[b * NIN + j];
        }
        __syncthreads();

#pragma unroll
        for (int kk = 0; kk < BK; kk++) {
            float4 a4 = *reinterpret_cast<const float4*>(&a_s[kk][rg * 4]);
            float av[4] = {a4.x, a4.y, a4.z, a4.w};
            float wv[5];
#pragma unroll
            for (int c = 0; c < 5; c++) wv[c] = w_s[kk][cg * 5 + c];
#pragma unroll
            for (int r = 0; r < 4; r++)
#pragma unroll
                for (int c = 0; c < 5; c++)
                    acc[r][c] = fmaf(av[r], wv[c], acc[r][c]);
        }
        __syncthreads();
    }

    float* out = g_buf1 + (size_t)t * (BATCH * H1);
#pragma unroll
    for (int r = 0; r < 4; r++) {
        int b = b0 + rg * 4 + r;
#pragma unroll
        for (int c = 0; c < 5; c++) {
            int col = cg * 5 + c;
            out[b * H1 + col] = acc[r][c] + b1[col];
        }
    }
}

// ---------------- layer-1 recurrence, in place: exc1 -> delayed outer ----------------
__global__ void r1_kernel() {
    const int gid = blockIdx.x * blockDim.x + threadIdx.x;   // (b,h) element
    const int S = BATCH * H1;
    float pi = 0.0f, po = 0.0f;
    for (int t = 0; t < T_STEPS; t++) {
        float* p = g_buf1 + (size_t)t * S + gid;
        float e = *p;
        *p = po;                               // o1d[t] = outer_{t-1}
        float in = e + pi * 0.9f;
        float ot = fmaxf(in - 1.0f, 0.0f);
        pi = (in - 1.0f > 0.0f) ? (in - 1.5f * in) : in;
        po = ot;
    }
}

// ---------------- GEMM2: exc2[t,b,k] = o1d @ W2 + b2 ----------------
#define E2T 256
__global__ __launch_bounds__(E2T)
void exc2_kernel(const float* __restrict__ W2, const float* __restrict__ b2) {
    __shared__ float w2s[H1][H2];
    __shared__ float b2s[H2];
    for (int idx = threadIdx.x; idx < H1 * H2; idx += E2T)
        w2s[idx / H2][idx % H2] = W2[idx];
    if (threadIdx.x < H2) b2s[threadIdx.x] = b2[threadIdx.x];
    __syncthreads();

    const int row = blockIdx.x * E2T + threadIdx.x;          // (t*B + b)
    const float4* a4 = reinterpret_cast<const float4*>(g_buf1 + (size_t)row * H1);

    float acc[H2];
#pragma unroll
    for (int k = 0; k < H2; k++) acc[k] = b2s[k];

#pragma unroll
    for (int kk4 = 0; kk4 < H1 / 4; kk4++) {
        float4 v = a4[kk4];
        float av[4] = {v.x, v.y, v.z, v.w};
#pragma unroll
        for (int c = 0; c < 4; c++) {
            int kk = kk4 * 4 + c;
#pragma unroll
            for (int k = 0; k < H2; k++)
                acc[k] = fmaf(av[c], w2s[kk][k], acc[k]);
        }
    }
    float* o = g_exc2 + (size_t)row * H2;
#pragma unroll
    for (int k = 0; k < H2; k++) o[k] = acc[k];
}

// ---------------- layer-2 recurrence + sum + log_softmax ----------------
__global__ __launch_bounds__(320)
void r2_kernel(float* __restrict__ out) {
    __shared__ float s[32][H2];
    const int tid = threadIdx.x;
    const int bl  = tid / H2;          // 0..31
    const int k   = tid % H2;
    const int b   = blockIdx.x * 32 + bl;
    const int col = b * H2 + k;

    float pi = 0.0f, acc = 0.0f;
    for (int t = 0; t < T_STEPS; t++) {
        if (t >= BEGIN) acc += pi;     // collects inner2 state BEFORE this step's update
        float e  = g_exc2[(size_t)t * (BATCH * H2) + col];
        float in = e + pi * 0.9f;
        pi = (in - 1.0f > 0.0f) ? (in - 1.5f * in) : in;
    }
    s[bl][k] = acc;
    __syncthreads();

    float m = -3.402823466e+38f;
#pragma unroll
    for (int j = 0; j < H2; j++) m = fmaxf(m, s[bl][j]);
    float sum = 0.0f;
#pragma unroll
    for (int j = 0; j < H2; j++) sum += expf(s[bl][j] - m);
    out[col] = (acc - m) - logf(sum);
}

// ---------------- launch ----------------
extern "C" void kernel_launch(void* const* d_in, const int* in_sizes, int n_in,
                              void* d_out, int out_size) {
    const float* x  = (const float*)d_in[0];   // [4096,1,28,28]
    const float* W1 = (const float*)d_in[1];   // [784,100]
    const float* b1 = (const float*)d_in[2];   // [100]
    const float* W2 = (const float*)d_in[3];   // [100,10]
    const float* b2 = (const float*)d_in[4];   // [10]
    float* out = (float*)d_out;                // [4096,10]

    init_keys_kernel<<<1, 128>>>();

    dim3 g1(BATCH / BM, T_STEPS);              // 64 x 100 CTAs
    gemm1_kernel<<<g1, GT>>>(x, W1, b1);

    r1_kernel<<<(BATCH * H1) / 256, 256>>>();

    exc2_kernel<<<(T_STEPS * BATCH) / E2T, E2T>>>(W2, b2);

    r2_kernel<<<BATCH / 32, 320>>>(out);
}

// round 9
// speedup vs baseline: 1.5003x; 1.5003x over previous
#include <cuda_runtime.h>
#include <cuda_fp16.h>
#include <cstdint>

#define T_STEPS 100
#define BATCH   4096
#define NIN     784
#define H1      100
#define H2      10
#define BEGIN   20

#define NPAD    128          // 16 n-tiles of 8
#define KPAD    832          // 13 chunks of 64
#define KC      64
#define NCHUNK  13
#define BM      32           // batch rows per CTA
#define GT      256          // 8 warps: (w&1)=row block, (w>>1)=n group of 4 tiles
#define SP      72           // smem row stride in fp16 elems (144B)

// ---------------- device scratch ----------------
__device__ uint2 g_keys[T_STEPS];
__device__ float g_buf1[(size_t)T_STEPS * H1 * BATCH];   // [t][h][b]; exc1 -> o1d in place
__device__ float g_exc2[(size_t)T_STEPS * H2 * BATCH];   // [t][k][b]
__device__ __half g_w1hi[NPAD * KPAD];                   // [n][k], zero padded
__device__ __half g_w1lo[NPAD * KPAD];

// ---------------- threefry2x32 (JAX-exact) ----------------
__device__ __forceinline__ void threefry2x32(uint32_t k0, uint32_t k1,
                                             uint32_t x0, uint32_t x1,
                                             uint32_t& o0, uint32_t& o1) {
    uint32_t k2 = k0 ^ k1 ^ 0x1BD11BDAu;
#define TFR(d) { x0 += x1; x1 = __funnelshift_l(x1, x1, (d)); x1 ^= x0; }
    x0 += k0; x1 += k1;
    TFR(13) TFR(15) TFR(26) TFR(6)
    x0 += k1; x1 += k2 + 1u;
    TFR(17) TFR(29) TFR(16) TFR(24)
    x0 += k2; x1 += k0 + 2u;
    TFR(13) TFR(15) TFR(26) TFR(6)
    x0 += k0; x1 += k1 + 3u;
    TFR(17) TFR(29) TFR(16) TFR(24)
    x0 += k1; x1 += k2 + 4u;
    TFR(13) TFR(15) TFR(26) TFR(6)
    x0 += k2; x1 += k0 + 5u;
#undef TFR
    o0 = x0; o1 = x1;
}
__global__ void init_keys_kernel() {
    int t = threadIdx.x;
    if (t < T_STEPS) {
        uint32_t w0, w1;
        threefry2x32(0u, 42u, 0u, (uint32_t)t, w0, w1);
        g_keys[t] = make_uint2(w0, w1);
    }
}
__device__ __forceinline__ float bits_to_uniform(uint32_t bits) {
    return __uint_as_float((bits >> 9) | 0x3f800000u) - 1.0f;
}

// ---------------- W1 -> fp16 hi/lo, transposed+padded [n][k] ----------------
__global__ void w1cvt_kernel(const float* __restrict__ W1) {
    int id = blockIdx.x * blockDim.x + threadIdx.x;
    if (id >= NPAD * KPAD) return;
    int n = id / KPAD, k = id % KPAD;
    float w = (n < H1 && k < NIN) ? W1[k * H1 + n] : 0.0f;
    __half hi = __float2half_rn(w);
    __half lo = __float2half_rn(w - __half2float(hi));
    g_w1hi[id] = hi;
    g_w1lo[id] = lo;
}

// ---------------- baseline-PTX MMA helpers ----------------
__device__ __forceinline__ uint32_t smem_u32(const void* p) {
    uint32_t a;
    asm("{ .reg .u64 t; cvta.to.shared.u64 t, %1; cvt.u32.u64 %0, t; }" : "=r"(a) : "l"(p));
    return a;
}
#define LDSM_X4(r0,r1,r2,r3,a) \
    asm volatile("ldmatrix.sync.aligned.m8n8.x4.shared.b16 {%0,%1,%2,%3}, [%4];" \
        : "=r"(r0), "=r"(r1), "=r"(r2), "=r"(r3) : "r"(a))
#define MMA16816(d, a0,a1,a2,a3, b0_,b1_) \
    asm volatile("mma.sync.aligned.m16n8k16.row.col.f32.f16.f16.f32 " \
        "{%0,%1,%2,%3}, {%4,%5,%6,%7}, {%8,%9}, {%0,%1,%2,%3};" \
        : "+f"((d)[0]), "+f"((d)[1]), "+f"((d)[2]), "+f"((d)[3]) \
        : "r"(a0), "r"(a1), "r"(a2), "r"(a3), "r"(b0_), "r"(b1_))

// ---------------- fused RNG + mma.sync GEMM1 (TC-rounding-safe) ----------------
__global__ __launch_bounds__(GT, 2)
void gemm1_mma_kernel(const float* __restrict__ x, const float* __restrict__ b1) {
    __shared__ float  s_bias[NPAD];
    __shared__ __half s_ahi[BM * SP];
    __shared__ __half s_alo[BM * SP];
    __shared__ __half s_bhi[NPAD * SP];
    __shared__ __half s_blo[NPAD * SP];

    const int tid = threadIdx.x;
    const int w   = tid >> 5;
    const int l   = tid & 31;
    const int rb  = w & 1;          // row block (16 rows)
    const int ng  = w >> 1;         // n group: tiles 4ng..4ng+3
    const int t   = blockIdx.y;
    const int b0  = blockIdx.x * BM;
    const uint2 key = g_keys[t];

    for (int i = tid; i < NPAD; i += GT)
        s_bias[i] = (i < H1) ? b1[i] : 0.0f;

    // lane-invariant ldmatrix addresses
    const int g  = l >> 3;
    const int lr = l & 7;
    const int rowA = 16 * rb + ((g & 1) << 3) + lr;
    const int kA   = (g >> 1) << 3;
    const uint32_t aHiB = smem_u32(s_ahi) + (uint32_t)(rowA * SP + kA) * 2;
    const uint32_t aLoB = smem_u32(s_alo) + (uint32_t)(rowA * SP + kA) * 2;
    // B pair p: tiles 4ng+2p, 4ng+2p+1
    uint32_t bHiB[2], bLoB[2];
#pragma unroll
    for (int p = 0; p < 2; p++) {
        int nB = 32 * ng + 16 * p + 8 * (g >> 1) + lr;
        int kB = (g & 1) << 3;
        bHiB[p] = smem_u32(s_bhi) + (uint32_t)(nB * SP + kB) * 2;
        bLoB[p] = smem_u32(s_blo) + (uint32_t)(nB * SP + kB) * 2;
    }

    float tot[4][4], chk[4][4], loa[4][4];
#pragma unroll
    for (int i = 0; i < 4; i++)
#pragma unroll
        for (int j = 0; j < 4; j++) { tot[i][j] = 0.0f; chk[i][j] = 0.0f; loa[i][j] = 0.0f; }

    const uint32_t* w1hi32 = (const uint32_t*)g_w1hi;
    const uint32_t* w1lo32 = (const uint32_t*)g_w1lo;

#pragma unroll 1
    for (int s = 0; s < NCHUNK; s++) {
        const int k0 = s * KC;

        // ---- fill B tile: [128 n][64 k] hi+lo (16 iters) ----
#pragma unroll
        for (int it = 0; it < (NPAD * KC / 2) / GT; it++) {
            int p  = tid + it * GT;
            int n  = p >> 5;
            int jp = p & 31;
            ((uint32_t*)s_bhi)[(n * SP) / 2 + jp] = w1hi32[n * (KPAD / 2) + k0 / 2 + jp];
            ((uint32_t*)s_blo)[(n * SP) / 2 + jp] = w1lo32[n * (KPAD / 2) + k0 / 2 + jp];
        }
        // ---- fill A tile: [32 b][64 j] fused threefry RNG, fp16 hi/lo (4 iters) ----
#pragma unroll 1
        for (int it = 0; it < (BM * KC / 2) / GT; it++) {
            int p  = tid + it * GT;
            int r  = p >> 5;
            int jp = p & 31;
            int b  = b0 + r;
            int j  = k0 + jp * 2;
            uint32_t h = 0, lo = 0;
            if (j < NIN) {
                float2 xv = *(const float2*)(x + b * NIN + j);
                uint32_t a0, a1, c0, c1;
                threefry2x32(key.x, key.y, 0u, (uint32_t)(b * NIN + j), a0, a1);
                threefry2x32(key.x, key.y, 0u, (uint32_t)(b * NIN + j + 1), c0, c1);
                float v0 = bits_to_uniform(a0 ^ a1) * xv.x;
                float v1 = bits_to_uniform(c0 ^ c1) * xv.y;
                __half h0 = __float2half_rn(v0);
                __half h1 = __float2half_rn(v1);
                __half l0 = __float2half_rn(v0 - __half2float(h0));
                __half l1 = __float2half_rn(v1 - __half2float(h1));
                h  = (uint32_t)*(uint16_t*)&h0 | ((uint32_t)*(uint16_t*)&h1 << 16);
                lo = (uint32_t)*(uint16_t*)&l0 | ((uint32_t)*(uint16_t*)&l1 << 16);
            }
            ((uint32_t*)s_ahi)[(r * SP) / 2 + jp] = h;
            ((uint32_t*)s_alo)[(r * SP) / 2 + jp] = lo;
        }
        __syncthreads();

        // ---- MMA: 4 k16-steps; hi chain -> chk (small C), lo chains -> loa ----
#pragma unroll 1
        for (int ks = 0; ks < KC / 16; ks++) {
            const uint32_t ko = (uint32_t)(ks * 32);
            uint32_t ah0, ah1, ah2, ah3, al0, al1, al2, al3;
            LDSM_X4(ah0, ah1, ah2, ah3, aHiB + ko);
            LDSM_X4(al0, al1, al2, al3, aLoB + ko);
#pragma unroll
            for (int p = 0; p < 2; p++) {
                uint32_t bh0, bh1, bh2, bh3, bl0, bl1, bl2, bl3;
                LDSM_X4(bh0, bh1, bh2, bh3, bHiB[p] + ko);
                LDSM_X4(bl0, bl1, bl2, bl3, bLoB[p] + ko);
                MMA16816(chk[2 * p],     ah0, ah1, ah2, ah3, bh0, bh1);
                MMA16816(chk[2 * p + 1], ah0, ah1, ah2, ah3, bh2, bh3);
                MMA16816(loa[2 * p],     al0, al1, al2, al3, bh0, bh1);
                MMA16816(loa[2 * p + 1], al0, al1, al2, al3, bh2, bh3);
                MMA16816(loa[2 * p],     ah0, ah1, ah2, ah3, bl0, bl1);
                MMA16816(loa[2 * p + 1], ah0, ah1, ah2, ah3, bl2, bl3);
            }
        }
        // drain hi chunk into fp32 totals (RN), rezero
#pragma unroll
        for (int i = 0; i < 4; i++)
#pragma unroll
            for (int j = 0; j < 4; j++) { tot[i][j] += chk[i][j]; chk[i][j] = 0.0f; }
        __syncthreads();
    }

    // ---- epilogue: (tot + lo + bias) -> g_buf1[t][c][b] ----
    float* outp = g_buf1 + (size_t)t * (H1 * BATCH);
    const int rlo = b0 + 16 * rb + (l >> 2);
#pragma unroll
    for (int i = 0; i < 4; i++) {
        int tile = 4 * ng + i;
        int c = 8 * tile + 2 * (l & 3);
        if (c < H1) {
            float v = tot[i][0] + loa[i][0] + s_bias[c];
            outp[(size_t)c * BATCH + rlo] = v;
            float v2 = tot[i][2] + loa[i][2] + s_bias[c];
            outp[(size_t)c * BATCH + rlo + 8] = v2;
        }
        if (c + 1 < H1) {
            float v = tot[i][1] + loa[i][1] + s_bias[c + 1];
            outp[(size_t)(c + 1) * BATCH + rlo] = v;
            float v2 = tot[i][3] + loa[i][3] + s_bias[c + 1];
            outp[(size_t)(c + 1) * BATCH + rlo + 8] = v2;
        }
    }
}

// ---------------- layer-1 recurrence in place: exc1 -> delayed outer ----------------
__global__ void r1_kernel() {
    const int gid = blockIdx.x * blockDim.x + threadIdx.x;   // (h,b)
    const int S = H1 * BATCH;
    float pi = 0.0f, po = 0.0f;
#pragma unroll 4
    for (int t = 0; t < T_STEPS; t++) {
        float* p = g_buf1 + (size_t)t * S + gid;
        float e = *p;
        *p = po;
        float in = e + pi * 0.9f;
        float ot = fmaxf(in - 1.0f, 0.0f);
        pi = (in - 1.0f > 0.0f) ? (in - 1.5f * in) : in;
        po = ot;
    }
}

// ---------------- GEMV2: exc2[t][k][b] = sum_h o1d[t][h][b] * W2[h][k] + b2 ----------------
#define E2T 256
__global__ __launch_bounds__(E2T)
void exc2_kernel(const float* __restrict__ W2, const float* __restrict__ b2) {
    __shared__ float w2s[H1][H2];
    __shared__ float b2s[H2];
    for (int i = threadIdx.x; i < H1 * H2; i += E2T) w2s[i / H2][i % H2] = W2[i];
    if (threadIdx.x < H2) b2s[threadIdx.x] = b2[threadIdx.x];
    __syncthreads();

    const int id = blockIdx.x * E2T + threadIdx.x;   // t*BATCH + b
    const int t = id / BATCH, b = id % BATCH;
    const float* src = g_buf1 + (size_t)t * (H1 * BATCH) + b;

    float acc[H2];
#pragma unroll
    for (int k = 0; k < H2; k++) acc[k] = b2s[k];
#pragma unroll 4
    for (int h = 0; h < H1; h++) {
        float a = src[(size_t)h * BATCH];
#pragma unroll
        for (int k = 0; k < H2; k++) acc[k] = fmaf(a, w2s[h][k], acc[k]);
    }
    float* dst = g_exc2 + (size_t)t * (H2 * BATCH) + b;
#pragma unroll
    for (int k = 0; k < H2; k++) dst[(size_t)k * BATCH] = acc[k];
}

// ---------------- layer-2 recurrence + sum + log_softmax ----------------
__global__ __launch_bounds__(320)
void r2_kernel(float* __restrict__ out) {
    __shared__ float s[H2][33];
    const int tid = threadIdx.x;
    const int bl = tid % 32;           // batch lane
    const int k  = tid / 32;           // 0..9
    const int b  = blockIdx.x * 32 + bl;

    float pi = 0.0f, acc = 0.0f;
    for (int t = 0; t < T_STEPS; t++) {
        if (t >= BEGIN) acc += pi;
        float e  = g_exc2[(size_t)t * (H2 * BATCH) + (size_t)k * BATCH + b];
        float in = e + pi * 0.9f;
        pi = (in - 1.0f > 0.0f) ? (in - 1.5f * in) : in;
    }
    s[k][bl] = acc;
    __syncthreads();

    float m = -3.402823466e+38f;
#pragma unroll
    for (int j = 0; j < H2; j++) m = fmaxf(m, s[j][bl]);
    float sum = 0.0f;
#pragma unroll
    for (int j = 0; j < H2; j++) sum += expf(s[j][bl] - m);
    out[b * H2 + k] = (acc - m) - logf(sum);
}

// ---------------- launch ----------------
extern "C" void kernel_launch(void* const* d_in, const int* in_sizes, int n_in,
                              void* d_out, int out_size) {
    const float* x  = (const float*)d_in[0];   // [4096,1,28,28]
    const float* W1 = (const float*)d_in[1];   // [784,100]
    const float* b1 = (const float*)d_in[2];   // [100]
    const float* W2 = (const float*)d_in[3];   // [100,10]
    const float* b2 = (const float*)d_in[4];   // [10]
    float* out = (float*)d_out;                // [4096,10]

    init_keys_kernel<<<1, 128>>>();
    w1cvt_kernel<<<(NPAD * KPAD + 255) / 256, 256>>>(W1);

    dim3 g1(BATCH / BM, T_STEPS);              // 128 x 100 CTAs
    gemm1_mma_kernel<<<g1, GT>>>(x, b1);

    r1_kernel<<<(H1 * BATCH) / 256, 256>>>();
    exc2_kernel<<<(T_STEPS * BATCH) / E2T, E2T>>>(W2, b2);
    r2_kernel<<<BATCH / 32, 320>>>(out);
}